// round 1
// baseline (speedup 1.0000x reference)
#include <cuda_runtime.h>

// Problem constants (fixed by the dataset)
#define DDIM 512
#define KCL  2048
#define NMAX 65536

// Scratch (no cudaMalloc allowed)
__device__ float g_c2[KCL];
__device__ float g_x2[NMAX];

// ---------------------------------------------------------------------------
// Row squared-norms: one warp per row, float4 loads, shfl reduce.
// ---------------------------------------------------------------------------
__global__ void c2_kernel(const float* __restrict__ cl) {
    int warp = (blockIdx.x * blockDim.x + threadIdx.x) >> 5;
    int lane = threadIdx.x & 31;
    if (warp >= KCL) return;
    const float4* r = (const float4*)(cl + (size_t)warp * DDIM);
    float s = 0.f;
    #pragma unroll 4
    for (int i = lane; i < DDIM / 4; i += 32) {
        float4 v = r[i];
        s += v.x * v.x + v.y * v.y + v.z * v.z + v.w * v.w;
    }
    #pragma unroll
    for (int o = 16; o; o >>= 1) s += __shfl_xor_sync(~0u, s, o);
    if (lane == 0) g_c2[warp] = s;
}

__global__ void x2_kernel(const float* __restrict__ x, int N) {
    int warp = (blockIdx.x * blockDim.x + threadIdx.x) >> 5;
    int lane = threadIdx.x & 31;
    if (warp >= N) return;
    const float4* r = (const float4*)(x + (size_t)warp * DDIM);
    float s = 0.f;
    #pragma unroll 4
    for (int i = lane; i < DDIM / 4; i += 32) {
        float4 v = r[i];
        s += v.x * v.x + v.y * v.y + v.z * v.z + v.w * v.w;
    }
    #pragma unroll
    for (int o = 16; o; o >>= 1) s += __shfl_xor_sync(~0u, s, o);
    if (lane == 0) g_x2[warp] = s;
}

// ---------------------------------------------------------------------------
// Zero the [loss | new_cluster | counts] region of the output.
// ---------------------------------------------------------------------------
__global__ void zero_kernel(float* p, int n) {
    int i = blockIdx.x * blockDim.x + threadIdx.x;
    if (i < n) p[i] = 0.f;
}

// ---------------------------------------------------------------------------
// Fused distance GEMM + argmin.
// Tile: BM=128 x-rows, BN=128 clusters, BK=16 over D. 256 threads, 8x8
// microtile per thread. Per chunk epilogue: s = c2[k] - 2*dot, update running
// (min, argmin). x2[row] is row-constant so it doesn't affect argmin; it is
// added only for the loss.
// ---------------------------------------------------------------------------
#define BM 128
#define BN 128
#define BK 16

__global__ __launch_bounds__(256)
void assign_kernel(const float* __restrict__ x, const float* __restrict__ cl,
                   float* __restrict__ out_idx, float* __restrict__ out_loss,
                   float invN) {
    __shared__ float As[BK][BM];   // transposed x tile
    __shared__ float Bs[BK][BN];   // transposed cluster tile
    __shared__ float c2s[BN];

    const int tid = threadIdx.x;
    const int tx = tid & 15;       // column group (8 cols)
    const int ty = tid >> 4;       // row group (8 rows)
    const int m0 = blockIdx.x * BM;

    float bv[8];
    int   bi[8];
    #pragma unroll
    for (int i = 0; i < 8; i++) { bv[i] = 3.4e38f; bi[i] = 0; }

    for (int kc = 0; kc < KCL; kc += BN) {
        __syncthreads();                      // protect c2s from prev epilogue
        if (tid < BN) c2s[tid] = g_c2[kc + tid];

        float acc[8][8];
        #pragma unroll
        for (int i = 0; i < 8; i++)
            #pragma unroll
            for (int j = 0; j < 8; j++) acc[i][j] = 0.f;

        for (int d0 = 0; d0 < DDIM; d0 += BK) {
            __syncthreads();
            // 512 float4 per operand, 2 per thread, stored transposed.
            #pragma unroll
            for (int q = 0; q < 2; q++) {
                int v   = tid * 2 + q;        // 0..511
                int row = v >> 2;             // 0..127
                int c4  = (v & 3) * 4;        // 0,4,8,12
                float4 t = *(const float4*)(x  + (size_t)(m0 + row) * DDIM + d0 + c4);
                As[c4 + 0][row] = t.x; As[c4 + 1][row] = t.y;
                As[c4 + 2][row] = t.z; As[c4 + 3][row] = t.w;
                float4 u = *(const float4*)(cl + (size_t)(kc + row) * DDIM + d0 + c4);
                Bs[c4 + 0][row] = u.x; Bs[c4 + 1][row] = u.y;
                Bs[c4 + 2][row] = u.z; Bs[c4 + 3][row] = u.w;
            }
            __syncthreads();

            #pragma unroll
            for (int kk = 0; kk < BK; kk++) {
                float a[8], b[8];
                *(float4*)&a[0] = *(const float4*)&As[kk][ty * 8];
                *(float4*)&a[4] = *(const float4*)&As[kk][ty * 8 + 4];
                *(float4*)&b[0] = *(const float4*)&Bs[kk][tx * 8];
                *(float4*)&b[4] = *(const float4*)&Bs[kk][tx * 8 + 4];
                #pragma unroll
                for (int i = 0; i < 8; i++)
                    #pragma unroll
                    for (int j = 0; j < 8; j++)
                        acc[i][j] = fmaf(a[i], b[j], acc[i][j]);
            }
        }

        // Epilogue: ascending column order -> strict '<' keeps lowest index.
        #pragma unroll
        for (int i = 0; i < 8; i++) {
            #pragma unroll
            for (int j = 0; j < 8; j++) {
                float s = fmaf(-2.f, acc[i][j], c2s[tx * 8 + j]);
                if (s < bv[i]) { bv[i] = s; bi[i] = kc + tx * 8 + j; }
            }
        }
    }

    // Reduce (min, argmin) across the 16 tx lanes (16-lane shfl segments).
    float lsum = 0.f;
    #pragma unroll
    for (int i = 0; i < 8; i++) {
        float v = bv[i];
        int   ix = bi[i];
        #pragma unroll
        for (int o = 8; o; o >>= 1) {
            float v2 = __shfl_xor_sync(~0u, v, o, 16);
            int   i2 = __shfl_xor_sync(~0u, ix, o, 16);
            if (v2 < v || (v2 == v && i2 < ix)) { v = v2; ix = i2; }
        }
        if (tx == 0) {
            int row = m0 + ty * 8 + i;
            out_idx[row] = (float)ix;
            lsum += (v + g_x2[row]) * invN;
        }
    }
    if (tx == 0) atomicAdd(out_loss, lsum);
}

// ---------------------------------------------------------------------------
// Segment scatter-sum: one warp per x row, float atomics to new_cluster.
// ---------------------------------------------------------------------------
__global__ void segsum_kernel(const float* __restrict__ x,
                              const float* __restrict__ idxf,
                              float* __restrict__ newc,
                              float* __restrict__ cnt, int N) {
    int warp = (blockIdx.x * blockDim.x + threadIdx.x) >> 5;
    int lane = threadIdx.x & 31;
    if (warp >= N) return;
    int k = (int)idxf[warp];
    const float4* row = (const float4*)(x + (size_t)warp * DDIM);
    float* dst = newc + (size_t)k * DDIM;
    #pragma unroll 4
    for (int i = lane; i < DDIM / 4; i += 32) {
        float4 v = row[i];
        atomicAdd(dst + i * 4 + 0, v.x);
        atomicAdd(dst + i * 4 + 1, v.y);
        atomicAdd(dst + i * 4 + 2, v.z);
        atomicAdd(dst + i * 4 + 3, v.w);
    }
    if (lane == 0) atomicAdd(cnt + k, 1.0f);
}

// ---------------------------------------------------------------------------
extern "C" void kernel_launch(void* const* d_in, const int* in_sizes, int n_in,
                              void* d_out, int out_size) {
    const float* x  = (const float*)d_in[0];
    const float* cl = (const float*)d_in[1];
    const int N = in_sizes[0] / DDIM;   // 65536
    float* out = (float*)d_out;

    // Layout: [idx (N) | loss (1) | new_cluster (K*D) | counts (K)]
    float* o_idx  = out;
    float* o_loss = out + N;
    float* o_newc = out + N + 1;
    float* o_cnt  = out + N + 1 + (size_t)KCL * DDIM;

    // 1. zero loss + new_cluster + counts
    int nz = 1 + KCL * DDIM + KCL;
    zero_kernel<<<(nz + 255) / 256, 256>>>(o_loss, nz);

    // 2. norms
    c2_kernel<<<(KCL * 32 + 255) / 256, 256>>>(cl);
    x2_kernel<<<((size_t)N * 32 + 255) / 256, 256>>>(x, N);

    // 3. fused distance GEMM + argmin (+ loss)
    assign_kernel<<<N / BM, 256>>>(x, cl, o_idx, o_loss, 1.0f / (float)N);

    // 4. segment scatter-sum
    segsum_kernel<<<((size_t)N * 32 + 255) / 256, 256>>>(x, o_idx, o_newc, o_cnt, N);
}

// round 3
// speedup vs baseline: 1.4116x; 1.4116x over previous
#include <cuda_runtime.h>
#include <cstdint>

// Problem constants
#define DDIM 512
#define KCL  2048
#define NTOT 65536

// GEMM tiling: CTA 128x128, k-chunk 32, 8 warps (2 M x 4 N), warp 64x32.
#define BM 128
#define BN 128
#define BK 32
#define NPASS (KCL / BN)   // 16 cluster passes
#define NCH   (DDIM / BK)  // 16 k-chunks per pass

#define STAGE_FLOATS (2 * 128 * 32)       // A tile + B tile
#define STAGE_BYTES  (STAGE_FLOATS * 4)   // 32 KB
#define SMEM_BYTES   (3 * STAGE_BYTES)    // 96 KB, 3-stage pipeline
#define A_OFF_F 0
#define B_OFF_F (128 * 32)

// Scratch (no cudaMalloc allowed)
__device__ float g_c2[KCL];
__device__ float g_x2[NTOT];

// ---------------------------------------------------------------------------
// Helpers
// ---------------------------------------------------------------------------
__device__ __forceinline__ uint32_t smem_to_u32(const void* p) {
    uint32_t a;
    asm("{ .reg .u64 t; cvta.to.shared.u64 t, %1; cvt.u32.u64 %0, t; }"
        : "=r"(a) : "l"(p));
    return a;
}
__device__ __forceinline__ void cp16(uint32_t dst, const void* src) {
    asm volatile("cp.async.cg.shared.global [%0], [%1], 16;"
                 :: "r"(dst), "l"(src) : "memory");
}
#define CP_COMMIT() asm volatile("cp.async.commit_group;" ::: "memory")
#define CP_WAIT(n)  asm volatile("cp.async.wait_group %0;" :: "n"(n) : "memory")

// 3xTF32 split: v = hi + lo (each a tf32-rounded value held as u32 bits)
__device__ __forceinline__ void split_tf32(float v, uint32_t& hi, uint32_t& lo) {
    uint32_t h;
    asm("cvt.rna.tf32.f32 %0, %1;" : "=r"(h) : "f"(v));
    float r = v - __uint_as_float(h);
    uint32_t l;
    asm("cvt.rna.tf32.f32 %0, %1;" : "=r"(l) : "f"(r));
    hi = h; lo = l;
}

__device__ __forceinline__ void mma8(float* c, const uint32_t* a, const uint32_t* b) {
    asm volatile(
        "mma.sync.aligned.m16n8k8.row.col.f32.tf32.tf32.f32 "
        "{%0,%1,%2,%3}, {%4,%5,%6,%7}, {%8,%9}, {%0,%1,%2,%3};"
        : "+f"(c[0]), "+f"(c[1]), "+f"(c[2]), "+f"(c[3])
        : "r"(a[0]), "r"(a[1]), "r"(a[2]), "r"(a[3]), "r"(b[0]), "r"(b[1]));
}

// ---------------------------------------------------------------------------
// Row squared-norms
// ---------------------------------------------------------------------------
__global__ void c2_kernel(const float* __restrict__ cl) {
    int warp = (blockIdx.x * blockDim.x + threadIdx.x) >> 5;
    int lane = threadIdx.x & 31;
    if (warp >= KCL) return;
    const float4* r = (const float4*)(cl + (size_t)warp * DDIM);
    float s = 0.f;
    #pragma unroll 4
    for (int i = lane; i < DDIM / 4; i += 32) {
        float4 v = r[i];
        s += v.x * v.x + v.y * v.y + v.z * v.z + v.w * v.w;
    }
    #pragma unroll
    for (int o = 16; o; o >>= 1) s += __shfl_xor_sync(~0u, s, o);
    if (lane == 0) g_c2[warp] = s;
}

__global__ void x2_kernel(const float* __restrict__ x, int N) {
    int warp = (blockIdx.x * blockDim.x + threadIdx.x) >> 5;
    int lane = threadIdx.x & 31;
    if (warp >= N) return;
    const float4* r = (const float4*)(x + (size_t)warp * DDIM);
    float s = 0.f;
    #pragma unroll 4
    for (int i = lane; i < DDIM / 4; i += 32) {
        float4 v = r[i];
        s += v.x * v.x + v.y * v.y + v.z * v.z + v.w * v.w;
    }
    #pragma unroll
    for (int o = 16; o; o >>= 1) s += __shfl_xor_sync(~0u, s, o);
    if (lane == 0) g_x2[warp] = s;
}

__global__ void zero_kernel(float* p, int n) {
    int i = blockIdx.x * blockDim.x + threadIdx.x;
    if (i < n) p[i] = 0.f;
}

// ---------------------------------------------------------------------------
// Chunk loader: A tile x[m0.., d0..d0+32), B tile cl[kc0.., d0..) both 128x32.
// Layout: row-major, 32 floats (128 B) per row, k swizzled by k ^ ((m&7)<<2).
// cp.async 16B: thread t, iter i -> v = t + 256*i, m = v>>3, q = v&7.
// gmem: 4 consecutive rows x 128B per warp (coalesced). smem: conflict-free.
// ---------------------------------------------------------------------------
__device__ __forceinline__ void load_chunk(const float* __restrict__ gA,
                                           const float* __restrict__ gB,
                                           int d0, uint32_t stage_u32, int tid) {
    #pragma unroll
    for (int t = 0; t < 4; t++) {
        int v = tid + t * 256;
        int m = v >> 3, q = v & 7;
        uint32_t so = (uint32_t)(m * 128 + 16 * (q ^ (m & 7)));
        cp16(stage_u32 + so, gA + (size_t)m * DDIM + d0 + q * 4);
        cp16(stage_u32 + B_OFF_F * 4 + so, gB + (size_t)m * DDIM + d0 + q * 4);
    }
}

// ---------------------------------------------------------------------------
// mma.sync tf32 (3x split) distance GEMM + fused argmin.
// ---------------------------------------------------------------------------
__global__ void __launch_bounds__(256, 1)
assign_mma(const float* __restrict__ x, const float* __restrict__ cl,
           float* __restrict__ out_idx, float* __restrict__ out_loss,
           float invN) {
    extern __shared__ float smem[];
    __shared__ float sval[128][4];
    __shared__ int   sidx[128][4];

    const uint32_t sb = smem_to_u32(smem);
    const int tid  = threadIdx.x;
    const int lane = tid & 31;
    const int wid  = tid >> 5;
    const int wm   = wid & 1;      // 2 warp rows (64 m each)
    const int wn   = wid >> 1;     // 4 warp cols (32 n each)
    const int g    = lane >> 2;    // 0..7
    const int t4   = lane & 3;     // 0..3
    const int m0   = blockIdx.x * BM;
    const int xr   = g << 2;       // per-thread swizzle xor

    float bv[8];
    int   bi[8];
    #pragma unroll
    for (int i = 0; i < 8; i++) { bv[i] = 3.4e38f; bi[i] = 0; }

    const float* gA = x + (size_t)m0 * DDIM;

    #pragma unroll 1
    for (int pass = 0; pass < NPASS; pass++) {
        const int kc0 = pass * BN;
        const float* gB = cl + (size_t)kc0 * DDIM;

        float acc[4][4][4];
        #pragma unroll
        for (int a = 0; a < 4; a++)
            #pragma unroll
            for (int b = 0; b < 4; b++)
                #pragma unroll
                for (int c = 0; c < 4; c++) acc[a][b][c] = 0.f;

        // pipeline prologue: chunks 0, 1
        load_chunk(gA, gB, 0, sb, tid);
        CP_COMMIT();
        load_chunk(gA, gB, BK, sb + STAGE_BYTES, tid);
        CP_COMMIT();

        #pragma unroll 1
        for (int dc = 0; dc < NCH; dc++) {
            CP_WAIT(1);          // chunk dc resident
            __syncthreads();     // also: everyone done with stage (dc+2)%3

            int ldc = dc + 2;
            if (ldc < NCH)
                load_chunk(gA, gB, ldc * BK, sb + (ldc % 3) * STAGE_BYTES, tid);
            CP_COMMIT();

            const float* stA = smem + (dc % 3) * STAGE_FLOATS;
            const float* stB = stA + B_OFF_F;

            #pragma unroll
            for (int ks = 0; ks < 4; ks++) {
                const int k0 = ks * 8 + t4;
                // B fragments for all 4 n-tiles (split hi/lo)
                uint32_t bh[4][2], bl[4][2];
                #pragma unroll
                for (int nt = 0; nt < 4; nt++) {
                    const float* rp = stB + (wn * 32 + nt * 8 + g) * 32;
                    split_tf32(rp[k0 ^ xr],       bh[nt][0], bl[nt][0]);
                    split_tf32(rp[(k0 + 4) ^ xr], bh[nt][1], bl[nt][1]);
                }
                #pragma unroll
                for (int mt = 0; mt < 4; mt++) {
                    const int r0 = wm * 64 + mt * 16 + g;
                    const float* rA0 = stA + r0 * 32;
                    const float* rA1 = stA + (r0 + 8) * 32;
                    uint32_t ah[4], al[4];
                    split_tf32(rA0[k0 ^ xr],       ah[0], al[0]);
                    split_tf32(rA1[k0 ^ xr],       ah[1], al[1]);
                    split_tf32(rA0[(k0 + 4) ^ xr], ah[2], al[2]);
                    split_tf32(rA1[(k0 + 4) ^ xr], ah[3], al[3]);
                    #pragma unroll
                    for (int nt = 0; nt < 4; nt++) {
                        mma8(acc[mt][nt], ah, bh[nt]);
                        mma8(acc[mt][nt], ah, bl[nt]);
                        mma8(acc[mt][nt], al, bh[nt]);
                    }
                }
            }
            __syncthreads();     // stage consumed before reuse
        }

        // Epilogue: s = c2[col] - 2*dot, fold into running per-row best.
        float c2v[8];
        #pragma unroll
        for (int cs = 0; cs < 8; cs++) {
            int col = kc0 + wn * 32 + (cs >> 1) * 8 + 2 * t4 + (cs & 1);
            c2v[cs] = __ldg(&g_c2[col]);
        }
        #pragma unroll
        for (int mt = 0; mt < 4; mt++) {
            #pragma unroll
            for (int hm = 0; hm < 2; hm++) {
                const int rs = mt * 2 + hm;
                #pragma unroll
                for (int nt = 0; nt < 4; nt++) {
                    #pragma unroll
                    for (int lsb = 0; lsb < 2; lsb++) {
                        float s = fmaf(-2.f, acc[mt][nt][hm * 2 + lsb],
                                       c2v[nt * 2 + lsb]);
                        int col = kc0 + wn * 32 + nt * 8 + 2 * t4 + lsb;
                        if (s < bv[rs]) { bv[rs] = s; bi[rs] = col; }
                    }
                }
            }
        }
    }

    // Reduce across the 4 lanes of each quad (t4), tie -> smaller index.
    #pragma unroll
    for (int rs = 0; rs < 8; rs++) {
        float v = bv[rs];
        int   ix = bi[rs];
        #pragma unroll
        for (int o = 1; o <= 2; o <<= 1) {
            float v2 = __shfl_xor_sync(~0u, v, o);
            int   i2 = __shfl_xor_sync(~0u, ix, o);
            if (v2 < v || (v2 == v && i2 < ix)) { v = v2; ix = i2; }
        }
        if (t4 == 0) {
            int row = wm * 64 + (rs >> 1) * 16 + (rs & 1) * 8 + g;
            sval[row][wn] = v;
            sidx[row][wn] = ix;
        }
    }
    __syncthreads();

    float lsum = 0.f;
    if (tid < 128) {
        float v = sval[tid][0];
        int  ix = sidx[tid][0];
        #pragma unroll
        for (int w = 1; w < 4; w++) {
            float v2 = sval[tid][w];
            int   i2 = sidx[tid][w];
            if (v2 < v || (v2 == v && i2 < ix)) { v = v2; ix = i2; }
        }
        int row = m0 + tid;
        out_idx[row] = (float)ix;
        lsum = (v + g_x2[row]) * invN;
    }
    #pragma unroll
    for (int o = 16; o; o >>= 1) lsum += __shfl_xor_sync(~0u, lsum, o);
    if (tid < 128 && lane == 0) atomicAdd(out_loss, lsum);
}

// ---------------------------------------------------------------------------
// Segment scatter-sum: one warp per x row.
// ---------------------------------------------------------------------------
__global__ void segsum_kernel(const float* __restrict__ x,
                              const float* __restrict__ idxf,
                              float* __restrict__ newc,
                              float* __restrict__ cnt, int N) {
    int warp = (blockIdx.x * blockDim.x + threadIdx.x) >> 5;
    int lane = threadIdx.x & 31;
    if (warp >= N) return;
    int k = (int)idxf[warp];
    const float4* row = (const float4*)(x + (size_t)warp * DDIM);
    float* dst = newc + (size_t)k * DDIM;
    #pragma unroll 4
    for (int i = lane; i < DDIM / 4; i += 32) {
        float4 v = row[i];
        atomicAdd(dst + i * 4 + 0, v.x);
        atomicAdd(dst + i * 4 + 1, v.y);
        atomicAdd(dst + i * 4 + 2, v.z);
        atomicAdd(dst + i * 4 + 3, v.w);
    }
    if (lane == 0) atomicAdd(cnt + k, 1.0f);
}

// ---------------------------------------------------------------------------
extern "C" void kernel_launch(void* const* d_in, const int* in_sizes, int n_in,
                              void* d_out, int out_size) {
    const float* x  = (const float*)d_in[0];
    const float* cl = (const float*)d_in[1];
    const int N = in_sizes[0] / DDIM;   // 65536
    float* out = (float*)d_out;

    // Layout: [idx (N) | loss (1) | new_cluster (K*D) | counts (K)]
    float* o_idx  = out;
    float* o_loss = out + N;
    float* o_newc = out + N + 1;
    float* o_cnt  = out + N + 1 + (size_t)KCL * DDIM;

    cudaFuncSetAttribute(assign_mma, cudaFuncAttributeMaxDynamicSharedMemorySize,
                         SMEM_BYTES);

    int nz = 1 + KCL * DDIM + KCL;
    zero_kernel<<<(nz + 255) / 256, 256>>>(o_loss, nz);

    c2_kernel<<<(KCL * 32 + 255) / 256, 256>>>(cl);
    x2_kernel<<<((size_t)N * 32 + 255) / 256, 256>>>(x, N);

    assign_mma<<<N / BM, 256, SMEM_BYTES>>>(x, cl, o_idx, o_loss,
                                            1.0f / (float)N);

    segsum_kernel<<<((size_t)N * 32 + 255) / 256, 256>>>(x, o_idx, o_newc,
                                                         o_cnt, N);
}